// round 5
// baseline (speedup 1.0000x reference)
#include <cuda_runtime.h>
#include <cuda_fp16.h>

// Problem constants (fixed by reference setup_inputs)
#define B_  8
#define C_  3
#define H_  1024
#define W_  1024
#define HO_ 256
#define WO_ 256
#define KS_ 3
#define KK_ (KS_*KS_)    // 9
#define SCALE_ 4
#define HP_ (H_ + 2)     // padded 1026
#define WP_ (W_ + 2)
#define PLANE_ (H_*W_)   // 1M

// fp16 NHWC4 scratch: (B, H, W, 4) halves = 67.1 MB
__device__ __half2 g_img_h4[B_ * H_ * W_ * 2];

// ---------------------------------------------------------------------------
// Pre-pass: NCHW fp32 -> NHWC4 fp16. Fully coalesced both sides.
// Each thread handles 2 consecutive pixels of one batch image.
// ---------------------------------------------------------------------------
__global__ __launch_bounds__(256)
void nchw_to_nhwc4h_kernel(const float* __restrict__ img)
{
    const int t = blockIdx.x * blockDim.x + threadIdx.x;  // 0 .. B*H*W/2-1
    const int px = t * 2;                                 // even pixel index
    const int b   = px >> 20;                             // / (H*W)
    const int rem = px & (PLANE_ - 1);

    const float* base = img + (long long)b * 3 * PLANE_ + rem;
    const float2 c0 = *(const float2*)(base);
    const float2 c1 = *(const float2*)(base + PLANE_);
    const float2 c2 = *(const float2*)(base + 2 * PLANE_);

    // pixel px  : (c0.x, c1.x, c2.x, 0)   pixel px+1: (c0.y, c1.y, c2.y, 0)
    __half2 p0lo = __floats2half2_rn(c0.x, c1.x);
    __half2 p0hi = __floats2half2_rn(c2.x, 0.f);
    __half2 p1lo = __floats2half2_rn(c0.y, c1.y);
    __half2 p1hi = __floats2half2_rn(c2.y, 0.f);

    // 16B store of 2 pixels
    uint4 v;
    v.x = *(unsigned*)&p0lo;
    v.y = *(unsigned*)&p0hi;
    v.z = *(unsigned*)&p1lo;
    v.w = *(unsigned*)&p1hi;
    *((uint4*)(g_img_h4 + (size_t)px * 2)) = v;
}

// reflect-map a padded index (0..n+1) to original index (0..n-1), pad=1
__device__ __forceinline__ int reflect_map(int i, int n) {
    int j = i - 1;
    j = (j < 0) ? -j : j;
    j = (j >= n) ? (2 * n - 2 - j) : j;
    return j;
}

// ---------------------------------------------------------------------------
// Main pass: gather half4 corners, fp32 accumulate.
// ---------------------------------------------------------------------------
__global__ __launch_bounds__(256, 5)
void adaptive_downsample_kernel(
    const float* __restrict__ kernels,    // (B,9,HO,WO)
    const float* __restrict__ offs_h,     // (B,9,HO,WO)
    const float* __restrict__ offs_v,     // (B,9,HO,WO)
    const float* __restrict__ offset_unit,// (1,)
    float* __restrict__ out)              // (B,C,HO,WO)
{
    const int ow = blockIdx.x * blockDim.x + threadIdx.x;  // 0..255
    const int oh = blockIdx.y * blockDim.y + threadIdx.y;  // 0..255
    const int b  = blockIdx.z;

    const float ou = __ldg(offset_unit);

    const float cy = ((float)oh + 0.5f) * (float)SCALE_ - 0.5f;
    const float cx = ((float)ow + 0.5f) * (float)SCALE_ - 0.5f;

    const int pix   = oh * WO_ + ow;
    const int plane = HO_ * WO_;                 // 65536
    const int auxb  = b * KK_ * plane + pix;     // fits int32 (max 4.7M)

    const __half2* imgb = g_img_h4 + ((size_t)b << 21);  // b * H*W*2 half2

    float acc0 = 0.f, acc1 = 0.f, acc2 = 0.f;

    #pragma unroll
    for (int k = 0; k < KK_; ++k) {
        const float kw  = __ldg(kernels + auxb + k * plane);
        const float ovv = __ldg(offs_v  + auxb + k * plane);
        const float ohh = __ldg(offs_h  + auxb + k * plane);

        const float py = cy + (float)(k / KS_) + ovv * ou;
        const float px = cx + (float)(k % KS_) + ohh * ou;

        const float y0f = floorf(py);
        const float x0f = floorf(px);
        const float beta  = py - y0f;
        const float alpha = px - x0f;

        int y0 = (int)y0f;  y0 = min(max(y0, 0), HP_ - 1);
        int y1 = min(y0 + 1, HP_ - 1);
        int x0 = (int)x0f;  x0 = min(max(x0, 0), WP_ - 1);
        int x1 = min(x0 + 1, WP_ - 1);

        const int ry0 = reflect_map(y0, H_);
        const int ry1 = reflect_map(y1, H_);
        const int rx0 = reflect_map(x0, W_);
        const int rx1 = reflect_map(x1, W_);

        const float w00 = (1.f - alpha) * (1.f - beta) * kw;
        const float w01 = alpha * (1.f - beta) * kw;
        const float w10 = (1.f - alpha) * beta * kw;
        const float w11 = alpha * beta * kw;

        // half4 corner loads (uint2 = 2x half2)
        const int i00 = ((ry0 << 10) + rx0) << 1;   // *2 half2 per pixel
        const int i01 = ((ry0 << 10) + rx1) << 1;
        const int i10 = ((ry1 << 10) + rx0) << 1;
        const int i11 = ((ry1 << 10) + rx1) << 1;

        {
            const uint2 v = __ldg((const uint2*)(imgb + i00));
            const float2 lo = __half22float2(*(__half2*)&v.x);
            const float2 hi = __half22float2(*(__half2*)&v.y);
            acc0 = fmaf(w00, lo.x, acc0);
            acc1 = fmaf(w00, lo.y, acc1);
            acc2 = fmaf(w00, hi.x, acc2);
        }
        {
            const uint2 v = __ldg((const uint2*)(imgb + i01));
            const float2 lo = __half22float2(*(__half2*)&v.x);
            const float2 hi = __half22float2(*(__half2*)&v.y);
            acc0 = fmaf(w01, lo.x, acc0);
            acc1 = fmaf(w01, lo.y, acc1);
            acc2 = fmaf(w01, hi.x, acc2);
        }
        {
            const uint2 v = __ldg((const uint2*)(imgb + i10));
            const float2 lo = __half22float2(*(__half2*)&v.x);
            const float2 hi = __half22float2(*(__half2*)&v.y);
            acc0 = fmaf(w10, lo.x, acc0);
            acc1 = fmaf(w10, lo.y, acc1);
            acc2 = fmaf(w10, hi.x, acc2);
        }
        {
            const uint2 v = __ldg((const uint2*)(imgb + i11));
            const float2 lo = __half22float2(*(__half2*)&v.x);
            const float2 hi = __half22float2(*(__half2*)&v.y);
            acc0 = fmaf(w11, lo.x, acc0);
            acc1 = fmaf(w11, lo.y, acc1);
            acc2 = fmaf(w11, hi.x, acc2);
        }
    }

    const int ob = b * C_ * plane + pix;
    out[ob]             = acc0;
    out[ob + plane]     = acc1;
    out[ob + 2 * plane] = acc2;
}

extern "C" void kernel_launch(void* const* d_in, const int* in_sizes, int n_in,
                              void* d_out, int out_size) {
    const float* img     = (const float*)d_in[0];
    const float* kernels = (const float*)d_in[1];
    const float* offs_h  = (const float*)d_in[2];
    const float* offs_v  = (const float*)d_in[3];
    const float* ou      = (const float*)d_in[4];
    float* out = (float*)d_out;

    // Pre-pass: B*H*W/2 threads, 2 px each
    const int n_threads = B_ * H_ * W_ / 2;     // 4.19M
    nchw_to_nhwc4h_kernel<<<n_threads / 256, 256>>>(img);

    dim3 block(32, 8, 1);
    dim3 grid(WO_ / 32, HO_ / 8, B_);
    adaptive_downsample_kernel<<<grid, block>>>(kernels, offs_h, offs_v, ou, out);
}